// round 2
// baseline (speedup 1.0000x reference)
#include <cuda_runtime.h>
#include <cstdint>

// Problem constants
#define S_DIM 10
#define H_DIM 100
#define N_DIM 50
#define BETA 3.0f
#define MAXA 5.0f

#define TPB 256
#define GRID 296           // 148 SMs * 2 resident blocks
#define ROWS_PER_BLOCK (TPB/2)

// Shared layout (floats):
//  wv2q : 1250 float4 [jp][np]          (5000 f)  off 0
//  wl2q : 2500 float4 [jp][n]           (10000 f) off 5000
//  wv1q : 250 float4  [jp][kp]          (1000 f)  off 15000
//  wl1q : 250 float4  [jp][kp]          (1000 f)  off 16000
//  bv1  : 100 f                                   off 17000
//  bl1  : 100 f                                   off 17100
//  bv2  : 50 f                                    off 17200
//  bl2  : 100 f [n][a]                            off 17250
#define SMEM_FLOATS 17350
#define SMEM_BYTES (SMEM_FLOATS*4)

__device__ __forceinline__ float2 ffma2(float2 a, float2 b, float2 c) {
    float2 d;
    asm("fma.rn.f32x2 %0, %1, %2, %3;"
        : "=l"(*reinterpret_cast<unsigned long long*>(&d))
        : "l"(*reinterpret_cast<unsigned long long*>(&a)),
          "l"(*reinterpret_cast<unsigned long long*>(&b)),
          "l"(*reinterpret_cast<unsigned long long*>(&c)));
    return d;
}

__device__ __forceinline__ float fast_tanh(float x) {
    float e = __expf(2.0f * x);
    return 1.0f - __fdividef(2.0f, e + 1.0f);
}

__global__ __launch_bounds__(TPB, 2)
void net_kernel(const float* __restrict__ s,  const float* __restrict__ a,
                const float* __restrict__ wv1, const float* __restrict__ bv1,
                const float* __restrict__ wv2, const float* __restrict__ bv2,
                const float* __restrict__ wl1, const float* __restrict__ bl1,
                const float* __restrict__ wl2, const float* __restrict__ bl2,
                float* __restrict__ out, int nrows)
{
    extern __shared__ float smem[];
    float4* sh_wv2q = (float4*)smem;                  // [jp*25+np], 1250
    float4* sh_wl2q = sh_wv2q + 1250;                 // [jp*50+n], 2500
    float4* sh_wv1q = sh_wl2q + 2500;                 // [jp*5+kp], 250
    float4* sh_wl1q = sh_wv1q + 250;                  // 250
    float*  sh_bv1  = (float*)(sh_wl1q + 250);        // 100
    float*  sh_bl1  = sh_bv1 + 100;                   // 100
    float*  sh_bv2  = sh_bl1 + 100;                   // 50
    float*  sh_bl2  = sh_bv2 + 50;                    // 100

    const int tid = threadIdx.x;

    // ---- Stage + pre-swizzle weights ----
    for (int i = tid; i < 100;  i += TPB) { sh_bv1[i] = bv1[i]; sh_bl1[i] = bl1[i]; sh_bl2[i] = bl2[i]; }
    for (int i = tid; i < 50;   i += TPB) { sh_bv2[i] = bv2[i]; }
    // wv2q[jp*25+np] = (wv2[2jp][2np], wv2[2jp][2np+1], wv2[2jp+1][2np], wv2[2jp+1][2np+1])
    for (int i = tid; i < 1250; i += TPB) {
        int jp = i / 25, np = i % 25;
        const float* p0 = wv2 + 100 * jp + 2 * np;   // wv2[2jp][2np]  (row stride 50)
        float2 q0 = *(const float2*)(p0);
        float2 q1 = *(const float2*)(p0 + 50);
        sh_wv2q[i] = make_float4(q0.x, q0.y, q1.x, q1.y);
    }
    // wl2 [n][h][a]: 4 contiguous floats = (n, 2jp, a0..1),(n, 2jp+1, a0..1)
    for (int i = tid; i < 2500; i += TPB) {
        int jp = i / 50, n = i % 50;
        sh_wl2q[i] = *(const float4*)(wl2 + n * 200 + 4 * jp);
    }
    // wv1q[jp*5+kp] = (wv1[2kp][2jp], wv1[2kp][2jp+1], wv1[2kp+1][2jp], wv1[2kp+1][2jp+1])
    for (int i = tid; i < 250; i += TPB) {
        int jp = i / 5, kp = i % 5;
        const float* p0 = wv1 + (2 * kp) * H_DIM + 2 * jp;
        float2 q0 = *(const float2*)(p0);
        float2 q1 = *(const float2*)(p0 + H_DIM);
        sh_wv1q[i] = make_float4(q0.x, q0.y, q1.x, q1.y);
        const float* p1 = wl1 + (2 * kp) * H_DIM + 2 * jp;
        float2 r0 = *(const float2*)(p1);
        float2 r1 = *(const float2*)(p1 + H_DIM);
        sh_wl1q[i] = make_float4(r0.x, r0.y, r1.x, r1.y);
    }
    __syncthreads();

    const int half   = tid & 1;             // which centroid half this thread owns
    const int npbase = half * 12;           // value np window: [npbase, npbase+13)
    const int nbase  = half * 24;           // loc n window:    [nbase, nbase+26)
    const int nlo    = half * 26;           // first VALID n for this thread

    const int stride = GRID * ROWS_PER_BLOCK;
    for (int b = blockIdx.x * ROWS_PER_BLOCK + (tid >> 1); b < nrows; b += stride) {
        // ---- load s row, a row (pair-threads load same row; L1 broadcast) ----
        float sr[S_DIM];
        {
            const float2* sp = (const float2*)(s + (size_t)b * S_DIM);
            #pragma unroll
            for (int k = 0; k < 5; k++) {
                float2 t = sp[k];
                sr[2 * k] = t.x; sr[2 * k + 1] = t.y;
            }
        }
        float2 av = ((const float2*)a)[b];

        // ---- Phase A: value tower ----
        float2 cv[13];
        #pragma unroll
        for (int i = 0; i < 13; i++) cv[i] = ((const float2*)sh_bv2)[npbase + i];

        for (int jp = 0; jp < 50; ++jp) {
            float2 hacc = ((const float2*)sh_bv1)[jp];
            const float4* wk = sh_wv1q + jp * 5;
            #pragma unroll
            for (int kp = 0; kp < 5; kp++) {
                float4 w4 = wk[kp];
                hacc = ffma2(make_float2(sr[2*kp],   sr[2*kp]),   make_float2(w4.x, w4.y), hacc);
                hacc = ffma2(make_float2(sr[2*kp+1], sr[2*kp+1]), make_float2(w4.z, w4.w), hacc);
            }
            float r0 = fmaxf(hacc.x, 0.0f), r1 = fmaxf(hacc.y, 0.0f);
            float2 h0 = make_float2(r0, r0), h1 = make_float2(r1, r1);
            const float4* wq = sh_wv2q + jp * 25 + npbase;
            #pragma unroll
            for (int i = 0; i < 13; i++) {
                float4 w4 = wq[i];
                cv[i] = ffma2(h0, make_float2(w4.x, w4.y), cv[i]);
                cv[i] = ffma2(h1, make_float2(w4.z, w4.w), cv[i]);
            }
        }

        // ---- Phase B: location tower ----
        float2 loc[26];
        #pragma unroll
        for (int i = 0; i < 26; i++) loc[i] = ((const float2*)sh_bl2)[nbase + i];

        for (int jp = 0; jp < 50; ++jp) {
            float2 hacc = ((const float2*)sh_bl1)[jp];
            const float4* wk = sh_wl1q + jp * 5;
            #pragma unroll
            for (int kp = 0; kp < 5; kp++) {
                float4 w4 = wk[kp];
                hacc = ffma2(make_float2(sr[2*kp],   sr[2*kp]),   make_float2(w4.x, w4.y), hacc);
                hacc = ffma2(make_float2(sr[2*kp+1], sr[2*kp+1]), make_float2(w4.z, w4.w), hacc);
            }
            float r0 = fmaxf(hacc.x, 0.0f), r1 = fmaxf(hacc.y, 0.0f);
            float2 h0 = make_float2(r0, r0), h1 = make_float2(r1, r1);
            const float4* wq = sh_wl2q + jp * 50 + nbase;
            #pragma unroll
            for (int i = 0; i < 26; i++) {
                float4 w4 = wq[i];
                loc[i] = ffma2(h0, make_float2(w4.x, w4.y), loc[i]);
                loc[i] = ffma2(h1, make_float2(w4.z, w4.w), loc[i]);
            }
        }

        // ---- Epilogue: tanh, RBF, masked partial sums, pair-combine ----
        float wsum = 0.0f, vsum = 0.0f;
        #pragma unroll
        for (int i = 0; i < 26; i++) {
            int n = nbase + i;
            float2 L = loc[i];
            float d0 = MAXA * fast_tanh(L.x) - av.x;
            float d1 = MAXA * fast_tanh(L.y) - av.y;
            float dist = sqrtf(d0 * d0 + d1 * d1);
            float e = __expf(-BETA * dist);
            float m = (n >= nlo) ? 1.0f : 0.0f;   // mask junk overlap on half 1
            e *= m;
            float cvv = (i & 1) ? cv[i >> 1].y : cv[i >> 1].x;
            wsum += e;
            vsum += e * cvv;
        }
        // combine the pair
        wsum += __shfl_xor_sync(0xffffffffu, wsum, 1);
        vsum += __shfl_xor_sync(0xffffffffu, vsum, 1);
        if (half == 0) out[b] = vsum / wsum;
    }
}

extern "C" void kernel_launch(void* const* d_in, const int* in_sizes, int n_in,
                              void* d_out, int out_size)
{
    const float* s   = (const float*)d_in[0];
    const float* a   = (const float*)d_in[1];
    const float* wv1 = (const float*)d_in[2];
    const float* bv1 = (const float*)d_in[3];
    const float* wv2 = (const float*)d_in[4];
    const float* bv2 = (const float*)d_in[5];
    const float* wl1 = (const float*)d_in[6];
    const float* bl1 = (const float*)d_in[7];
    const float* wl2 = (const float*)d_in[8];
    const float* bl2 = (const float*)d_in[9];
    float* out = (float*)d_out;

    int nrows = in_sizes[0] / S_DIM;

    cudaFuncSetAttribute(net_kernel, cudaFuncAttributeMaxDynamicSharedMemorySize, SMEM_BYTES);
    net_kernel<<<GRID, TPB, SMEM_BYTES>>>(s, a, wv1, bv1, wv2, bv2,
                                          wl1, bl1, wl2, bl2, out, nrows);
}

// round 3
// speedup vs baseline: 1.0010x; 1.0010x over previous
#include <cuda_runtime.h>
#include <cstdint>

// Problem constants
#define S_DIM 10
#define H_DIM 100
#define N_DIM 50
#define BETA 3.0f
#define MAXA 5.0f

#define TPB 256
#define GRID 296           // 148 SMs * 2 resident blocks
#define ROWS_PER_BLOCK (TPB/2)

// Shared layout (floats):
//  wv2q : 1250 float4 [jp][np]          (5000 f)  off 0
//  wl2q : 2500 float4 [jp][n]           (10000 f) off 5000
//  wv1q : 250 float4  [jp][kp]          (1000 f)  off 15000
//  wl1q : 250 float4  [jp][kp]          (1000 f)  off 16000
//  bv1  : 100 f                                   off 17000
//  bl1  : 100 f                                   off 17100
//  bv2  : 50 f                                    off 17200
//  bl2  : 100 f [n][a]                            off 17250
#define SMEM_FLOATS 17350
#define SMEM_BYTES (SMEM_FLOATS*4)

__device__ __forceinline__ float2 ffma2(float2 a, float2 b, float2 c) {
    float2 d;
    asm("fma.rn.f32x2 %0, %1, %2, %3;"
        : "=l"(*reinterpret_cast<unsigned long long*>(&d))
        : "l"(*reinterpret_cast<unsigned long long*>(&a)),
          "l"(*reinterpret_cast<unsigned long long*>(&b)),
          "l"(*reinterpret_cast<unsigned long long*>(&c)));
    return d;
}

__device__ __forceinline__ float fast_tanh(float x) {
    float e = __expf(2.0f * x);
    return 1.0f - __fdividef(2.0f, e + 1.0f);
}

__global__ __launch_bounds__(TPB, 2)
void net_kernel(const float* __restrict__ s,  const float* __restrict__ a,
                const float* __restrict__ wv1, const float* __restrict__ bv1,
                const float* __restrict__ wv2, const float* __restrict__ bv2,
                const float* __restrict__ wl1, const float* __restrict__ bl1,
                const float* __restrict__ wl2, const float* __restrict__ bl2,
                float* __restrict__ out, int nrows)
{
    extern __shared__ float smem[];
    float4* sh_wv2q = (float4*)smem;                  // [jp*25+np], 1250
    float4* sh_wl2q = sh_wv2q + 1250;                 // [jp*50+n], 2500
    float4* sh_wv1q = sh_wl2q + 2500;                 // [jp*5+kp], 250
    float4* sh_wl1q = sh_wv1q + 250;                  // 250
    float*  sh_bv1  = (float*)(sh_wl1q + 250);        // 100
    float*  sh_bl1  = sh_bv1 + 100;                   // 100
    float*  sh_bv2  = sh_bl1 + 100;                   // 50
    float*  sh_bl2  = sh_bv2 + 50;                    // 100

    const int tid = threadIdx.x;

    // ---- Stage + pre-swizzle weights ----
    for (int i = tid; i < 100;  i += TPB) { sh_bv1[i] = bv1[i]; sh_bl1[i] = bl1[i]; sh_bl2[i] = bl2[i]; }
    for (int i = tid; i < 50;   i += TPB) { sh_bv2[i] = bv2[i]; }
    // wv2q[jp*25+np] = (wv2[2jp][2np], wv2[2jp][2np+1], wv2[2jp+1][2np], wv2[2jp+1][2np+1])
    for (int i = tid; i < 1250; i += TPB) {
        int jp = i / 25, np = i % 25;
        const float* p0 = wv2 + 100 * jp + 2 * np;   // wv2[2jp][2np]  (row stride 50)
        float2 q0 = *(const float2*)(p0);
        float2 q1 = *(const float2*)(p0 + 50);
        sh_wv2q[i] = make_float4(q0.x, q0.y, q1.x, q1.y);
    }
    // wl2 [n][h][a]: 4 contiguous floats = (n, 2jp, a0..1),(n, 2jp+1, a0..1)
    for (int i = tid; i < 2500; i += TPB) {
        int jp = i / 50, n = i % 50;
        sh_wl2q[i] = *(const float4*)(wl2 + n * 200 + 4 * jp);
    }
    // wv1q[jp*5+kp] = (wv1[2kp][2jp], wv1[2kp][2jp+1], wv1[2kp+1][2jp], wv1[2kp+1][2jp+1])
    for (int i = tid; i < 250; i += TPB) {
        int jp = i / 5, kp = i % 5;
        const float* p0 = wv1 + (2 * kp) * H_DIM + 2 * jp;
        float2 q0 = *(const float2*)(p0);
        float2 q1 = *(const float2*)(p0 + H_DIM);
        sh_wv1q[i] = make_float4(q0.x, q0.y, q1.x, q1.y);
        const float* p1 = wl1 + (2 * kp) * H_DIM + 2 * jp;
        float2 r0 = *(const float2*)(p1);
        float2 r1 = *(const float2*)(p1 + H_DIM);
        sh_wl1q[i] = make_float4(r0.x, r0.y, r1.x, r1.y);
    }
    __syncthreads();

    const int half   = tid & 1;             // which centroid half this thread owns
    const int npbase = half * 12;           // value np window: [npbase, npbase+13)
    const int nbase  = half * 24;           // loc n window:    [nbase, nbase+26)
    const int nlo    = half * 26;           // first VALID n for this thread

    const int stride = GRID * ROWS_PER_BLOCK;
    for (int b = blockIdx.x * ROWS_PER_BLOCK + (tid >> 1); b < nrows; b += stride) {
        // ---- load s row, a row (pair-threads load same row; L1 broadcast) ----
        float sr[S_DIM];
        {
            const float2* sp = (const float2*)(s + (size_t)b * S_DIM);
            #pragma unroll
            for (int k = 0; k < 5; k++) {
                float2 t = sp[k];
                sr[2 * k] = t.x; sr[2 * k + 1] = t.y;
            }
        }
        float2 av = ((const float2*)a)[b];

        // ---- Phase A: value tower ----
        float2 cv[13];
        #pragma unroll
        for (int i = 0; i < 13; i++) cv[i] = ((const float2*)sh_bv2)[npbase + i];

        for (int jp = 0; jp < 50; ++jp) {
            float2 hacc = ((const float2*)sh_bv1)[jp];
            const float4* wk = sh_wv1q + jp * 5;
            #pragma unroll
            for (int kp = 0; kp < 5; kp++) {
                float4 w4 = wk[kp];
                hacc = ffma2(make_float2(sr[2*kp],   sr[2*kp]),   make_float2(w4.x, w4.y), hacc);
                hacc = ffma2(make_float2(sr[2*kp+1], sr[2*kp+1]), make_float2(w4.z, w4.w), hacc);
            }
            float r0 = fmaxf(hacc.x, 0.0f), r1 = fmaxf(hacc.y, 0.0f);
            float2 h0 = make_float2(r0, r0), h1 = make_float2(r1, r1);
            const float4* wq = sh_wv2q + jp * 25 + npbase;
            #pragma unroll
            for (int i = 0; i < 13; i++) {
                float4 w4 = wq[i];
                cv[i] = ffma2(h0, make_float2(w4.x, w4.y), cv[i]);
                cv[i] = ffma2(h1, make_float2(w4.z, w4.w), cv[i]);
            }
        }

        // ---- Phase B: location tower ----
        float2 loc[26];
        #pragma unroll
        for (int i = 0; i < 26; i++) loc[i] = ((const float2*)sh_bl2)[nbase + i];

        for (int jp = 0; jp < 50; ++jp) {
            float2 hacc = ((const float2*)sh_bl1)[jp];
            const float4* wk = sh_wl1q + jp * 5;
            #pragma unroll
            for (int kp = 0; kp < 5; kp++) {
                float4 w4 = wk[kp];
                hacc = ffma2(make_float2(sr[2*kp],   sr[2*kp]),   make_float2(w4.x, w4.y), hacc);
                hacc = ffma2(make_float2(sr[2*kp+1], sr[2*kp+1]), make_float2(w4.z, w4.w), hacc);
            }
            float r0 = fmaxf(hacc.x, 0.0f), r1 = fmaxf(hacc.y, 0.0f);
            float2 h0 = make_float2(r0, r0), h1 = make_float2(r1, r1);
            const float4* wq = sh_wl2q + jp * 50 + nbase;
            #pragma unroll
            for (int i = 0; i < 26; i++) {
                float4 w4 = wq[i];
                loc[i] = ffma2(h0, make_float2(w4.x, w4.y), loc[i]);
                loc[i] = ffma2(h1, make_float2(w4.z, w4.w), loc[i]);
            }
        }

        // ---- Epilogue: tanh, RBF, masked partial sums, pair-combine ----
        float wsum = 0.0f, vsum = 0.0f;
        #pragma unroll
        for (int i = 0; i < 26; i++) {
            int n = nbase + i;
            float2 L = loc[i];
            float d0 = MAXA * fast_tanh(L.x) - av.x;
            float d1 = MAXA * fast_tanh(L.y) - av.y;
            float dist = sqrtf(d0 * d0 + d1 * d1);
            float e = __expf(-BETA * dist);
            float m = (n >= nlo) ? 1.0f : 0.0f;   // mask junk overlap on half 1
            e *= m;
            float cvv = (i & 1) ? cv[i >> 1].y : cv[i >> 1].x;
            wsum += e;
            vsum += e * cvv;
        }
        // combine the pair
        wsum += __shfl_xor_sync(0xffffffffu, wsum, 1);
        vsum += __shfl_xor_sync(0xffffffffu, vsum, 1);
        if (half == 0) out[b] = vsum / wsum;
    }
}

extern "C" void kernel_launch(void* const* d_in, const int* in_sizes, int n_in,
                              void* d_out, int out_size)
{
    const float* s   = (const float*)d_in[0];
    const float* a   = (const float*)d_in[1];
    const float* wv1 = (const float*)d_in[2];
    const float* bv1 = (const float*)d_in[3];
    const float* wv2 = (const float*)d_in[4];
    const float* bv2 = (const float*)d_in[5];
    const float* wl1 = (const float*)d_in[6];
    const float* bl1 = (const float*)d_in[7];
    const float* wl2 = (const float*)d_in[8];
    const float* bl2 = (const float*)d_in[9];
    float* out = (float*)d_out;

    int nrows = in_sizes[0] / S_DIM;

    cudaFuncSetAttribute(net_kernel, cudaFuncAttributeMaxDynamicSharedMemorySize, SMEM_BYTES);
    net_kernel<<<GRID, TPB, SMEM_BYTES>>>(s, a, wv1, bv1, wv2, bv2,
                                          wl1, bl1, wl2, bl2, out, nrows);
}

// round 5
// speedup vs baseline: 3.6405x; 3.6367x over previous
#include <cuda_runtime.h>
#include <cuda_bf16.h>
#include <cstdint>

#define TPB 256
#define GRIDX 148
#define BETA 3.0f
#define MAXA 5.0f

// smem byte offsets
#define B1H   0        // 224 rows x 48B
#define B1L   10752
#define B2VH  21504    // 56 rows x 240B
#define B2VL  34944
#define B2LH  48384    // 104 rows x 240B
#define B2LL  73344
#define HH    98304    // 128 rows x 240B
#define HL    129024
#define SMEM_BYTES 159744

__device__ __forceinline__ void split2(float e0, float e1, uint32_t& H, uint32_t& L) {
    __nv_bfloat16 h0 = __float2bfloat16(e0);
    __nv_bfloat16 h1 = __float2bfloat16(e1);
    float r0 = e0 - __bfloat162float(h0);
    float r1 = e1 - __bfloat162float(h1);
    __nv_bfloat16 l0 = __float2bfloat16(r0);
    __nv_bfloat16 l1 = __float2bfloat16(r1);
    H = (uint32_t)*(unsigned short*)&h0 | ((uint32_t)*(unsigned short*)&h1 << 16);
    L = (uint32_t)*(unsigned short*)&l0 | ((uint32_t)*(unsigned short*)&l1 << 16);
}

__device__ __forceinline__ void st_split(char* sm, int offH, int offL, int bo, float v) {
    __nv_bfloat16 h = __float2bfloat16(v);
    float r = v - __bfloat162float(h);
    __nv_bfloat16 l = __float2bfloat16(r);
    *(unsigned short*)(sm + offH + bo) = *(unsigned short*)&h;
    *(unsigned short*)(sm + offL + bo) = *(unsigned short*)&l;
}

__device__ __forceinline__ void mma16816(float* c, const uint32_t* a, uint32_t b0, uint32_t b1) {
    asm volatile(
        "mma.sync.aligned.m16n8k16.row.col.f32.bf16.bf16.f32 "
        "{%0,%1,%2,%3}, {%4,%5,%6,%7}, {%8,%9}, {%0,%1,%2,%3};"
        : "+f"(c[0]), "+f"(c[1]), "+f"(c[2]), "+f"(c[3])
        : "r"(a[0]), "r"(a[1]), "r"(a[2]), "r"(a[3]), "r"(b0), "r"(b1));
}

__device__ __forceinline__ float fast_tanh(float x) {
    float e = __expf(2.0f * x);
    return 1.0f - __fdividef(2.0f, e + 1.0f);
}

__global__ __launch_bounds__(TPB, 1)
void net_kernel(const float* __restrict__ s,  const float* __restrict__ a,
                const float* __restrict__ wv1, const float* __restrict__ bv1,
                const float* __restrict__ wv2, const float* __restrict__ bv2,
                const float* __restrict__ wl1, const float* __restrict__ bl1,
                const float* __restrict__ wl2, const float* __restrict__ bl2,
                float* __restrict__ out, int nrows)
{
    extern __shared__ __align__(16) char sm[];
    const int tid  = threadIdx.x;
    const int w    = tid >> 5;
    const int lane = tid & 31;
    const int g    = lane >> 2;   // groupID (row within m16 half)
    const int q    = lane & 3;    // threadID in group

    // ---- zero all smem (covers every pad) ----
    for (int i = tid * 16; i < SMEM_BYTES; i += TPB * 16)
        *(float4*)(sm + i) = make_float4(0.f, 0.f, 0.f, 0.f);
    __syncthreads();

    // ---- stage weights (bf16 hi/lo split) ----
    // B1: value rows 0..99, loc rows 112..211; k<10 = w1[k][n], k=10 = bias
    for (int i = tid; i < 2200; i += TPB) {
        int tower = i / 1100, rem = i % 1100, n = rem / 11, k = rem % 11;
        float v = (k < 10) ? (tower ? wl1[k * 100 + n] : wv1[k * 100 + n])
                           : (tower ? bl1[n] : bv1[n]);
        int row = tower ? 112 + n : n;
        st_split(sm, B1H, B1L, row * 48 + k * 2, v);
    }
    // B2v: permuted rows sigma(c); k<100 = wv2[k][sig], k=100 = bias
    for (int i = tid; i < 56 * 101; i += TPB) {
        int c = i / 101, k = i % 101;
        int sig = (c % 8) / 2 + 8 * (c / 8) + 4 * (c % 2);
        if (sig < 50) {
            float v = (k < 100) ? wv2[k * 50 + sig] : bv2[sig];
            st_split(sm, B2VH, B2VL, c * 240 + k * 2, v);
        }
    }
    // B2l: row c = 2n+comp
    for (int i = tid; i < 100 * 101; i += TPB) {
        int c = i / 101, k = i % 101;
        float v = (k < 100) ? wl2[(c >> 1) * 200 + k * 2 + (c & 1)] : bl2[c];
        st_split(sm, B2LH, B2LL, c * 240 + k * 2, v);
    }
    __syncthreads();

    const int ntiles = (nrows + 127) >> 7;
    const int lr0 = w * 16 + g;      // local h row (this thread's a-frag rows)
    const int lr1 = lr0 + 8;

    for (int tile = blockIdx.x; tile < ntiles; tile += GRIDX) {
        const int grow0 = (tile << 7) + lr0;
        const int grow1 = grow0 + 8;

        // ---- build GEMM1 A-fragments from global s ----
        uint32_t saH[4], saL[4];
        {
            float2 p0 = make_float2(0.f, 0.f), p1 = p0, e0 = p0, e1 = p0;
            if (grow0 < nrows) p0 = *(const float2*)(s + (size_t)grow0 * 10 + 2 * q);
            if (grow1 < nrows) p1 = *(const float2*)(s + (size_t)grow1 * 10 + 2 * q);
            if (q == 0) {
                if (grow0 < nrows) e0 = *(const float2*)(s + (size_t)grow0 * 10 + 8);
                if (grow1 < nrows) e1 = *(const float2*)(s + (size_t)grow1 * 10 + 8);
            } else if (q == 1) {
                e0.x = 1.0f; e1.x = 1.0f;   // bias column (k=10)
            }
            split2(p0.x, p0.y, saH[0], saL[0]);
            split2(p1.x, p1.y, saH[1], saL[1]);
            split2(e0.x, e0.y, saH[2], saL[2]);
            split2(e1.x, e1.y, saH[3], saL[3]);
        }
        // a (action) rows, loaded early
        float2 av0 = make_float2(0.f, 0.f), av1 = av0;
        if (grow0 < nrows) av0 = ((const float2*)a)[grow0];
        if (grow1 < nrows) av1 = ((const float2*)a)[grow1];

        // ================= VALUE tower =================
        float dv[13][4];
        #pragma unroll
        for (int j = 0; j < 13; j++) { dv[j][0]=0.f; dv[j][1]=0.f; dv[j][2]=0.f; dv[j][3]=0.f; }
        #pragma unroll
        for (int j = 0; j < 13; j++) {
            int bo = (8 * j + g) * 48 + q * 4;
            uint32_t bH0 = *(const uint32_t*)(sm + B1H + bo);
            uint32_t bH1 = *(const uint32_t*)(sm + B1H + bo + 16);
            uint32_t bL0 = *(const uint32_t*)(sm + B1L + bo);
            uint32_t bL1 = *(const uint32_t*)(sm + B1L + bo + 16);
            mma16816(dv[j], saH, bH0, bH1);
            mma16816(dv[j], saH, bL0, bL1);
            mma16816(dv[j], saL, bH0, bH1);
        }
        // relu + split-store hv into h planes
        __syncwarp();
        #pragma unroll
        for (int j = 0; j < 13; j++) {
            int cb = 16 * j + 4 * q;
            uint32_t Hh, Ll;
            split2(fmaxf(dv[j][0], 0.f), fmaxf(dv[j][1], 0.f), Hh, Ll);
            *(uint32_t*)(sm + HH + lr0 * 240 + cb) = Hh;
            *(uint32_t*)(sm + HL + lr0 * 240 + cb) = Ll;
            split2(fmaxf(dv[j][2], 0.f), fmaxf(dv[j][3], 0.f), Hh, Ll);
            *(uint32_t*)(sm + HH + lr1 * 240 + cb) = Hh;
            *(uint32_t*)(sm + HL + lr1 * 240 + cb) = Ll;
        }
        if (lane < 16) *(unsigned short*)(sm + HH + (w * 16 + lane) * 240 + 200) = 0x3F80;
        __syncwarp();

        // GEMM2v: cv[7][4]
        float cv[7][4];
        #pragma unroll
        for (int j = 0; j < 7; j++) { cv[j][0]=0.f; cv[j][1]=0.f; cv[j][2]=0.f; cv[j][3]=0.f; }
        #pragma unroll
        for (int ks = 0; ks < 7; ks++) {
            int ab = 32 * ks + 4 * q;
            uint32_t aH[4], aL[4];
            aH[0] = *(const uint32_t*)(sm + HH + lr0 * 240 + ab);
            aH[1] = *(const uint32_t*)(sm + HH + lr1 * 240 + ab);
            aH[2] = *(const uint32_t*)(sm + HH + lr0 * 240 + ab + 16);
            aH[3] = *(const uint32_t*)(sm + HH + lr1 * 240 + ab + 16);
            aL[0] = *(const uint32_t*)(sm + HL + lr0 * 240 + ab);
            aL[1] = *(const uint32_t*)(sm + HL + lr1 * 240 + ab);
            aL[2] = *(const uint32_t*)(sm + HL + lr0 * 240 + ab + 16);
            aL[3] = *(const uint32_t*)(sm + HL + lr1 * 240 + ab + 16);
            #pragma unroll
            for (int j = 0; j < 7; j++) {
                int bo = (8 * j + g) * 240 + ab;
                uint32_t bH0 = *(const uint32_t*)(sm + B2VH + bo);
                uint32_t bH1 = *(const uint32_t*)(sm + B2VH + bo + 16);
                uint32_t bL0 = *(const uint32_t*)(sm + B2VL + bo);
                uint32_t bL1 = *(const uint32_t*)(sm + B2VL + bo + 16);
                mma16816(cv[j], aH, bH0, bH1);
                mma16816(cv[j], aH, bL0, bL1);
                mma16816(cv[j], aL, bH0, bH1);
            }
        }

        // ================= LOC tower =================
        float dl[13][4];
        #pragma unroll
        for (int j = 0; j < 13; j++) { dl[j][0]=0.f; dl[j][1]=0.f; dl[j][2]=0.f; dl[j][3]=0.f; }
        #pragma unroll
        for (int j = 0; j < 13; j++) {
            int bo = (112 + 8 * j + g) * 48 + q * 4;
            uint32_t bH0 = *(const uint32_t*)(sm + B1H + bo);
            uint32_t bH1 = *(const uint32_t*)(sm + B1H + bo + 16);
            uint32_t bL0 = *(const uint32_t*)(sm + B1L + bo);
            uint32_t bL1 = *(const uint32_t*)(sm + B1L + bo + 16);
            mma16816(dl[j], saH, bH0, bH1);
            mma16816(dl[j], saH, bL0, bL1);
            mma16816(dl[j], saL, bH0, bH1);
        }
        __syncwarp();   // all reads of hv done before overwriting h
        #pragma unroll
        for (int j = 0; j < 13; j++) {
            int cb = 16 * j + 4 * q;
            uint32_t Hh, Ll;
            split2(fmaxf(dl[j][0], 0.f), fmaxf(dl[j][1], 0.f), Hh, Ll);
            *(uint32_t*)(sm + HH + lr0 * 240 + cb) = Hh;
            *(uint32_t*)(sm + HL + lr0 * 240 + cb) = Ll;
            split2(fmaxf(dl[j][2], 0.f), fmaxf(dl[j][3], 0.f), Hh, Ll);
            *(uint32_t*)(sm + HH + lr1 * 240 + cb) = Hh;
            *(uint32_t*)(sm + HL + lr1 * 240 + cb) = Ll;
        }
        if (lane < 16) *(unsigned short*)(sm + HH + (w * 16 + lane) * 240 + 200) = 0x3F80;
        __syncwarp();

        // GEMM2l: lc[13][4]
        float lc[13][4];
        #pragma unroll
        for (int j = 0; j < 13; j++) { lc[j][0]=0.f; lc[j][1]=0.f; lc[j][2]=0.f; lc[j][3]=0.f; }
        #pragma unroll
        for (int ks = 0; ks < 7; ks++) {
            int ab = 32 * ks + 4 * q;
            uint32_t aH[4], aL[4];
            aH[0] = *(const uint32_t*)(sm + HH + lr0 * 240 + ab);
            aH[1] = *(const uint32_t*)(sm + HH + lr1 * 240 + ab);
            aH[2] = *(const uint32_t*)(sm + HH + lr0 * 240 + ab + 16);
            aH[3] = *(const uint32_t*)(sm + HH + lr1 * 240 + ab + 16);
            aL[0] = *(const uint32_t*)(sm + HL + lr0 * 240 + ab);
            aL[1] = *(const uint32_t*)(sm + HL + lr1 * 240 + ab);
            aL[2] = *(const uint32_t*)(sm + HL + lr0 * 240 + ab + 16);
            aL[3] = *(const uint32_t*)(sm + HL + lr1 * 240 + ab + 16);
            #pragma unroll
            for (int j = 0; j < 13; j++) {
                int bo = (8 * j + g) * 240 + ab;
                uint32_t bH0 = *(const uint32_t*)(sm + B2LH + bo);
                uint32_t bH1 = *(const uint32_t*)(sm + B2LH + bo + 16);
                uint32_t bL0 = *(const uint32_t*)(sm + B2LL + bo);
                uint32_t bL1 = *(const uint32_t*)(sm + B2LL + bo + 16);
                mma16816(lc[j], aH, bH0, bH1);
                mma16816(lc[j], aH, bL0, bL1);
                mma16816(lc[j], aL, bH0, bH1);
            }
        }
        __syncwarp();   // h reads complete before next tile's stores

        // ================= epilogue =================
        // thread q, tile jp: loc cols (2q+8jp, +1) = centroid q+4jp (x,y)
        // cv for that centroid = cv[jp>>1][(jp&1)] (rows g) / [2+(jp&1)] (rows g+8)
        float ws0 = 0.f, vs0 = 0.f, ws1 = 0.f, vs1 = 0.f;
        #pragma unroll
        for (int jp = 0; jp < 13; jp++) {
            const bool valid = (q + 4 * jp) < 50;
            {
                float t0 = MAXA * fast_tanh(lc[jp][0]) - av0.x;
                float t1 = MAXA * fast_tanh(lc[jp][1]) - av0.y;
                float e = valid ? __expf(-BETA * sqrtf(t0 * t0 + t1 * t1)) : 0.f;
                float cvv = (jp & 1) ? cv[jp >> 1][1] : cv[jp >> 1][0];
                ws0 += e; vs0 += e * cvv;
            }
            {
                float t0 = MAXA * fast_tanh(lc[jp][2]) - av1.x;
                float t1 = MAXA * fast_tanh(lc[jp][3]) - av1.y;
                float e = valid ? __expf(-BETA * sqrtf(t0 * t0 + t1 * t1)) : 0.f;
                float cvv = (jp & 1) ? cv[jp >> 1][3] : cv[jp >> 1][2];
                ws1 += e; vs1 += e * cvv;
            }
        }
        ws0 += __shfl_xor_sync(0xffffffffu, ws0, 1);
        vs0 += __shfl_xor_sync(0xffffffffu, vs0, 1);
        ws1 += __shfl_xor_sync(0xffffffffu, ws1, 1);
        vs1 += __shfl_xor_sync(0xffffffffu, vs1, 1);
        ws0 += __shfl_xor_sync(0xffffffffu, ws0, 2);
        vs0 += __shfl_xor_sync(0xffffffffu, vs0, 2);
        ws1 += __shfl_xor_sync(0xffffffffu, ws1, 2);
        vs1 += __shfl_xor_sync(0xffffffffu, vs1, 2);
        if (q == 0) {
            if (grow0 < nrows) out[grow0] = vs0 / ws0;
            if (grow1 < nrows) out[grow1] = vs1 / ws1;
        }
    }
}

extern "C" void kernel_launch(void* const* d_in, const int* in_sizes, int n_in,
                              void* d_out, int out_size)
{
    const float* s   = (const float*)d_in[0];
    const float* a   = (const float*)d_in[1];
    const float* wv1 = (const float*)d_in[2];
    const float* bv1 = (const float*)d_in[3];
    const float* wv2 = (const float*)d_in[4];
    const float* bv2 = (const float*)d_in[5];
    const float* wl1 = (const float*)d_in[6];
    const float* bl1 = (const float*)d_in[7];
    const float* wl2 = (const float*)d_in[8];
    const float* bl2 = (const float*)d_in[9];
    float* out = (float*)d_out;

    int nrows = in_sizes[0] / 10;

    cudaFuncSetAttribute(net_kernel, cudaFuncAttributeMaxDynamicSharedMemorySize, SMEM_BYTES);
    net_kernel<<<GRIDX, TPB, SMEM_BYTES>>>(s, a, wv1, bv1, wv2, bv2,
                                           wl1, bl1, wl2, bl2, out, nrows);
}

// round 6
// speedup vs baseline: 4.8306x; 1.3269x over previous
#include <cuda_runtime.h>
#include <cuda_bf16.h>
#include <cstdint>

#define TPB 384
#define GRIDX 148
#define TILE_M 192
#define BETA 3.0f
#define MAXA 5.0f

// smem: interleaved bf16 hi/lo B layouts, 16B unit = [H0,H1,L0,L1] per (ks,q)
#define B1OFF  0        // 224 rows x 64B
#define B2VOFF 14336    // 56 rows x 448B
#define B2LOFF 39424    // 104 rows x 448B
#define SMEM_BYTES 86016

// pack two f32 -> bf16x2 (lo=x, hi=y) plus residual word
__device__ __forceinline__ void split_pack(float x, float y, uint32_t& H, uint32_t& L) {
    asm("cvt.rn.bf16x2.f32 %0, %1, %2;" : "=r"(H) : "f"(y), "f"(x));
    float xh = __uint_as_float(H << 16);
    float yh = __uint_as_float(H & 0xFFFF0000u);
    float xr = x - xh, yr = y - yh;
    asm("cvt.rn.bf16x2.f32 %0, %1, %2;" : "=r"(L) : "f"(yr), "f"(xr));
}
__device__ __forceinline__ void relu_split(float x, float y, uint32_t& H, uint32_t& L) {
    split_pack(fmaxf(x, 0.f), fmaxf(y, 0.f), H, L);
}

// staging: write bf16 hi at byte bH, lo at bH+8
__device__ __forceinline__ void st_split(char* sm, int bH, float v) {
    __nv_bfloat16 h = __float2bfloat16(v);
    float r = v - __bfloat162float(h);
    __nv_bfloat16 l = __float2bfloat16(r);
    *(unsigned short*)(sm + bH)     = *(unsigned short*)&h;
    *(unsigned short*)(sm + bH + 8) = *(unsigned short*)&l;
}
// interleaved byte offsets (H slot; L at +8)
__device__ __forceinline__ int b1_byte(int row, int k) {
    int w = k >> 1;
    return row * 64 + (w & 3) * 16 + ((w >> 2) << 2) + ((k & 1) << 1);
}
__device__ __forceinline__ int b2_byte(int row, int k) {
    int w = k >> 1;
    return row * 448 + (w >> 3) * 64 + ((w & 3) << 4) + (((w >> 2) & 1) << 2) + ((k & 1) << 1);
}

__device__ __forceinline__ void mma16816(float* c, const uint32_t* a, uint32_t b0, uint32_t b1) {
    asm volatile(
        "mma.sync.aligned.m16n8k16.row.col.f32.bf16.bf16.f32 "
        "{%0,%1,%2,%3}, {%4,%5,%6,%7}, {%8,%9}, {%0,%1,%2,%3};"
        : "+f"(c[0]), "+f"(c[1]), "+f"(c[2]), "+f"(c[3])
        : "r"(a[0]), "r"(a[1]), "r"(a[2]), "r"(a[3]), "r"(b0), "r"(b1));
}

__device__ __forceinline__ float fast_tanh(float x) {
    float e = __expf(2.0f * x);
    return 1.0f - __fdividef(2.0f, e + 1.0f);
}

__global__ __launch_bounds__(TPB, 1)
void net_kernel(const float* __restrict__ s,  const float* __restrict__ a,
                const float* __restrict__ wv1, const float* __restrict__ bv1,
                const float* __restrict__ wv2, const float* __restrict__ bv2,
                const float* __restrict__ wl1, const float* __restrict__ bl1,
                const float* __restrict__ wl2, const float* __restrict__ bl2,
                float* __restrict__ out, int nrows)
{
    extern __shared__ __align__(16) char sm[];
    const int tid  = threadIdx.x;
    const int w    = tid >> 5;
    const int lane = tid & 31;
    const int g    = lane >> 2;
    const int q    = lane & 3;

    // zero all smem (covers every pad row/col)
    for (int i = tid * 16; i < SMEM_BYTES; i += TPB * 16)
        *(float4*)(sm + i) = make_float4(0.f, 0.f, 0.f, 0.f);
    __syncthreads();

    // ---- stage weights ----
    // B1: value rows 0..99, loc rows 112..211; k<10 = w1[k][n], k=10 = bias
    for (int i = tid; i < 2200; i += TPB) {
        int tower = i / 1100, rem = i % 1100, n = rem / 11, k = rem % 11;
        float v = (k < 10) ? (tower ? wl1[k * 100 + n] : wv1[k * 100 + n])
                           : (tower ? bl1[n] : bv1[n]);
        st_split(sm, B1OFF + b1_byte(tower ? 112 + n : n, k), v);
    }
    // B2v: permuted rows sigma(c); k<100 = wv2[k][sig], k=100 = bias
    for (int i = tid; i < 56 * 101; i += TPB) {
        int c = i / 101, k = i % 101;
        int sig = (c % 8) / 2 + 8 * (c / 8) + 4 * (c % 2);
        if (sig < 50)
            st_split(sm, B2VOFF + b2_byte(c, k), (k < 100) ? wv2[k * 50 + sig] : bv2[sig]);
    }
    // B2l: row c = 2n+comp
    for (int i = tid; i < 100 * 101; i += TPB) {
        int c = i / 101, k = i % 101;
        float v = (k < 100) ? wl2[(c >> 1) * 200 + k * 2 + (c & 1)] : bl2[c];
        st_split(sm, B2LOFF + b2_byte(c, k), v);
    }
    __syncthreads();

    const int ntiles = (nrows + TILE_M - 1) / TILE_M;
    const int lr0 = w * 16 + g;

    for (int tile = blockIdx.x; tile < ntiles; tile += GRIDX) {
        const int grow0 = tile * TILE_M + lr0;
        const int grow1 = grow0 + 8;

        // ---- GEMM1 A-fragments from global s (K=16: s cols 0..9, bias at 10) ----
        uint32_t saH[4], saL[4];
        {
            float2 p0 = make_float2(0.f, 0.f), p1 = p0, e0 = p0, e1 = p0;
            if (grow0 < nrows) p0 = *(const float2*)(s + (size_t)grow0 * 10 + 2 * q);
            if (grow1 < nrows) p1 = *(const float2*)(s + (size_t)grow1 * 10 + 2 * q);
            if (q == 0) {
                if (grow0 < nrows) e0 = *(const float2*)(s + (size_t)grow0 * 10 + 8);
                if (grow1 < nrows) e1 = *(const float2*)(s + (size_t)grow1 * 10 + 8);
            } else if (q == 1) {
                e0.x = 1.0f; e1.x = 1.0f;
            }
            split_pack(p0.x, p0.y, saH[0], saL[0]);
            split_pack(p1.x, p1.y, saH[1], saL[1]);
            split_pack(e0.x, e0.y, saH[2], saL[2]);
            split_pack(e1.x, e1.y, saH[3], saL[3]);
        }
        float2 av0 = make_float2(0.f, 0.f), av1 = av0;
        if (grow0 < nrows) av0 = ((const float2*)a)[grow0];
        if (grow1 < nrows) av1 = ((const float2*)a)[grow1];

        // ================= VALUE tower =================
        float dv[13][4];
        #pragma unroll
        for (int j = 0; j < 13; j++) { dv[j][0]=0.f; dv[j][1]=0.f; dv[j][2]=0.f; dv[j][3]=0.f; }
        #pragma unroll
        for (int j = 0; j < 13; j++) {
            uint4 bb = *(const uint4*)(sm + B1OFF + (8 * j + g) * 64 + q * 16);
            mma16816(dv[j], saH, bb.x, bb.y);
            mma16816(dv[j], saH, bb.z, bb.w);
            mma16816(dv[j], saL, bb.x, bb.y);
        }
        // relu + split: D-frag -> A-frag (registers only)
        uint32_t vaH[7][4], vaL[7][4];
        #pragma unroll
        for (int ks = 0; ks < 6; ks++) {
            relu_split(dv[2*ks][0],   dv[2*ks][1],   vaH[ks][0], vaL[ks][0]);
            relu_split(dv[2*ks][2],   dv[2*ks][3],   vaH[ks][1], vaL[ks][1]);
            relu_split(dv[2*ks+1][0], dv[2*ks+1][1], vaH[ks][2], vaL[ks][2]);
            relu_split(dv[2*ks+1][2], dv[2*ks+1][3], vaH[ks][3], vaL[ks][3]);
        }
        relu_split(dv[12][0], dv[12][1], vaH[6][0], vaL[6][0]);
        relu_split(dv[12][2], dv[12][3], vaH[6][1], vaL[6][1]);
        if (q == 2) { vaH[6][0] = 0x3F80u; vaL[6][0] = 0u; vaH[6][1] = 0x3F80u; vaL[6][1] = 0u; }
        vaH[6][2] = 0u; vaH[6][3] = 0u; vaL[6][2] = 0u; vaL[6][3] = 0u;

        // GEMM2v: cv = hv x B2v^T
        float cv[7][4];
        #pragma unroll
        for (int j = 0; j < 7; j++) { cv[j][0]=0.f; cv[j][1]=0.f; cv[j][2]=0.f; cv[j][3]=0.f; }
        #pragma unroll
        for (int ks = 0; ks < 7; ks++) {
            #pragma unroll
            for (int j = 0; j < 7; j++) {
                uint4 bb = *(const uint4*)(sm + B2VOFF + (8 * j + g) * 448 + ks * 64 + q * 16);
                mma16816(cv[j], vaH[ks], bb.x, bb.y);
                mma16816(cv[j], vaH[ks], bb.z, bb.w);
                mma16816(cv[j], vaL[ks], bb.x, bb.y);
            }
        }

        // ================= LOC tower =================
        float dl[13][4];
        #pragma unroll
        for (int j = 0; j < 13; j++) { dl[j][0]=0.f; dl[j][1]=0.f; dl[j][2]=0.f; dl[j][3]=0.f; }
        #pragma unroll
        for (int j = 0; j < 13; j++) {
            uint4 bb = *(const uint4*)(sm + B1OFF + (112 + 8 * j + g) * 64 + q * 16);
            mma16816(dl[j], saH, bb.x, bb.y);
            mma16816(dl[j], saH, bb.z, bb.w);
            mma16816(dl[j], saL, bb.x, bb.y);
        }
        uint32_t laH[7][4], laL[7][4];
        #pragma unroll
        for (int ks = 0; ks < 6; ks++) {
            relu_split(dl[2*ks][0],   dl[2*ks][1],   laH[ks][0], laL[ks][0]);
            relu_split(dl[2*ks][2],   dl[2*ks][3],   laH[ks][1], laL[ks][1]);
            relu_split(dl[2*ks+1][0], dl[2*ks+1][1], laH[ks][2], laL[ks][2]);
            relu_split(dl[2*ks+1][2], dl[2*ks+1][3], laH[ks][3], laL[ks][3]);
        }
        relu_split(dl[12][0], dl[12][1], laH[6][0], laL[6][0]);
        relu_split(dl[12][2], dl[12][3], laH[6][1], laL[6][1]);
        if (q == 2) { laH[6][0] = 0x3F80u; laL[6][0] = 0u; laH[6][1] = 0x3F80u; laL[6][1] = 0u; }
        laH[6][2] = 0u; laH[6][3] = 0u; laL[6][2] = 0u; laL[6][3] = 0u;

        // GEMM2l: locpre = hl x B2l^T
        float lc[13][4];
        #pragma unroll
        for (int j = 0; j < 13; j++) { lc[j][0]=0.f; lc[j][1]=0.f; lc[j][2]=0.f; lc[j][3]=0.f; }
        #pragma unroll
        for (int ks = 0; ks < 7; ks++) {
            #pragma unroll
            for (int j = 0; j < 13; j++) {
                uint4 bb = *(const uint4*)(sm + B2LOFF + (8 * j + g) * 448 + ks * 64 + q * 16);
                mma16816(lc[j], laH[ks], bb.x, bb.y);
                mma16816(lc[j], laH[ks], bb.z, bb.w);
                mma16816(lc[j], laL[ks], bb.x, bb.y);
            }
        }

        // ================= epilogue =================
        // tile j, thread q: centroid n = 4j+q; cols (2q,2q+1) = (x,y); rows g and g+8
        float ws0 = 0.f, vs0 = 0.f, ws1 = 0.f, vs1 = 0.f;
        #pragma unroll
        for (int j = 0; j < 13; j++) {
            const bool valid = (4 * j + q) < 50;
            {
                float tx = MAXA * fast_tanh(lc[j][0]) - av0.x;
                float ty = MAXA * fast_tanh(lc[j][1]) - av0.y;
                float d2 = tx * tx + ty * ty;
                float dist = d2 * rsqrtf(d2 + 1e-30f);
                float e = valid ? __expf(-BETA * dist) : 0.f;
                float c = (j & 1) ? cv[j >> 1][1] : cv[j >> 1][0];
                ws0 += e; vs0 += e * c;
            }
            {
                float tx = MAXA * fast_tanh(lc[j][2]) - av1.x;
                float ty = MAXA * fast_tanh(lc[j][3]) - av1.y;
                float d2 = tx * tx + ty * ty;
                float dist = d2 * rsqrtf(d2 + 1e-30f);
                float e = valid ? __expf(-BETA * dist) : 0.f;
                float c = (j & 1) ? cv[j >> 1][3] : cv[j >> 1][2];
                ws1 += e; vs1 += e * c;
            }
        }
        ws0 += __shfl_xor_sync(0xffffffffu, ws0, 1);
        vs0 += __shfl_xor_sync(0xffffffffu, vs0, 1);
        ws1 += __shfl_xor_sync(0xffffffffu, ws1, 1);
        vs1 += __shfl_xor_sync(0xffffffffu, vs1, 1);
        ws0 += __shfl_xor_sync(0xffffffffu, ws0, 2);
        vs0 += __shfl_xor_sync(0xffffffffu, vs0, 2);
        ws1 += __shfl_xor_sync(0xffffffffu, ws1, 2);
        vs1 += __shfl_xor_sync(0xffffffffu, vs1, 2);
        if (q == 0) {
            if (grow0 < nrows) out[grow0] = vs0 / ws0;
            if (grow1 < nrows) out[grow1] = vs1 / ws1;
        }
    }
}

extern "C" void kernel_launch(void* const* d_in, const int* in_sizes, int n_in,
                              void* d_out, int out_size)
{
    const float* s   = (const float*)d_in[0];
    const float* a   = (const float*)d_in[1];
    const float* wv1 = (const float*)d_in[2];
    const float* bv1 = (const float*)d_in[3];
    const float* wv2 = (const float*)d_in[4];
    const float* bv2 = (const float*)d_in[5];
    const float* wl1 = (const float*)d_in[6];
    const float* bl1 = (const float*)d_in[7];
    const float* wl2 = (const float*)d_in[8];
    const float* bl2 = (const float*)d_in[9];
    float* out = (float*)d_out;

    int nrows = in_sizes[0] / 10;

    cudaFuncSetAttribute(net_kernel, cudaFuncAttributeMaxDynamicSharedMemorySize, SMEM_BYTES);
    net_kernel<<<GRIDX, TPB, SMEM_BYTES>>>(s, a, wv1, bv1, wv2, bv2,
                                           wl1, bl1, wl2, bl2, out, nrows);
}